// round 17
// baseline (speedup 1.0000x reference)
#include <cuda_runtime.h>
#include <cstdint>

typedef unsigned long long u64;

#define NQ 16384
#define NB 128
#define NF 64
#define HD 128
#define EPSF 1e-8f

#define THREADS 768
#define WARPS_PER_CTA 24
#define PAIRS_PER_CTA 12
#define MAXQ 5

// Packed probe tables (prep output). Pair p couples b=p and b=p+64.
// g_probeA[f][p] = {P_real[p], P_real[p+64], P_imag[p], P_imag[p+64]}
// g_probeB[f][p] = {w[p],      w[p+64],      mw[p],     mw[p+64]}
__device__ float g_probeA[NF * 64 * 4];
__device__ float g_probeB[NF * 64 * 4];

// ---------- f32x2 helpers ----------
__device__ __forceinline__ u64 f2pk(float lo, float hi) {
    u64 r; asm("mov.b64 %0, {%1,%2};" : "=l"(r) : "f"(lo), "f"(hi)); return r;
}
__device__ __forceinline__ void f2upk(float& lo, float& hi, u64 v) {
    asm("mov.b64 {%0,%1}, %2;" : "=f"(lo), "=f"(hi) : "l"(v));
}
__device__ __forceinline__ u64 f2add(u64 a, u64 b) {
    u64 d; asm("add.rn.f32x2 %0, %1, %2;" : "=l"(d) : "l"(a), "l"(b)); return d;
}
__device__ __forceinline__ u64 f2fma(u64 a, u64 b, u64 c) {
    u64 d; asm("fma.rn.f32x2 %0, %1, %2, %3;" : "=l"(d) : "l"(a), "l"(b), "l"(c)); return d;
}
__device__ __forceinline__ float sqrt_apx(float x) {
    float r; asm("sqrt.approx.f32 %0, %1;" : "=f"(r) : "f"(x)); return r;
}
__device__ __forceinline__ float rcp_apx(float x) {
    float r; asm("rcp.approx.f32 %0, %1;" : "=f"(r) : "f"(x)); return r;
}
__device__ __forceinline__ uint32_t su32(const void* p) {
    uint32_t a;
    asm("{ .reg .u64 t; cvta.to.shared.u64 t, %1; cvt.u32.u64 %0, t; }"
        : "=r"(a) : "l"(p));
    return a;
}

// ---------- prep: one block per probe b, one thread per f ----------
__global__ __launch_bounds__(64)
void prep_kernel(const float* __restrict__ probes,
                 const float* __restrict__ angles,
                 const float* __restrict__ qw,
                 const float* __restrict__ qmw) {
    __shared__ float red[2];
    const int b = blockIdx.x;   // 0..127
    const int f = threadIdx.x;  // 0..63
    const int warp = f >> 5;
    const int lane = f & 31;

    float x0 = probes[b * HD + f];
    float x1 = probes[b * HD + NF + f];
    float ss = fmaf(x0, x0, x1 * x1);
#pragma unroll
    for (int o = 16; o; o >>= 1) ss += __shfl_xor_sync(0xffffffffu, ss, o);
    if (lane == 0) red[warp] = ss;
    __syncthreads();
    float inv = 1.0f / (sqrtf(red[0] + red[1]) + EPSF);

    float pr = x0 * inv;
    float pi = x1 * inv;
    float c, s;
    __sincosf(angles[f], &s, &c);
    float Pr = pr * c - pi * s;
    float Pi = pr * s + pi * c;
    float xw = qw[b * NF + f];
    float sp = fmaxf(xw, 0.0f) + __logf(1.0f + __expf(-fabsf(xw)));
    float w = -sp;
    float mw = qmw[b * NF + f];

    int p = b & 63;
    int hi = b >> 6;
    int base = (f * 64 + p) * 4;
    g_probeA[base + 0 + hi] = Pr;
    g_probeA[base + 2 + hi] = Pi;
    g_probeB[base + 0 + hi] = w;
    g_probeB[base + 2 + hi] = mw;
}

// ---------- SMEM layout (float offsets) ----------
#define OFF_SA  0                           // probeA: 16384 floats (64KB)
#define OFF_SB  16384                       // probeB: 16384 floats (64KB)
#define OFF_QT  32768                       // q-tables: 12 pairs * 5q * 64f * 4 = 15360 floats (60KB)
#define OFF_QN  48128                       // per-warp qn scratch: 24*128 = 3072 floats (12KB)
#define SMEM_FLOATS 51200                   // 200 KB

// f-loop over a batch of JN q's, software-pipelined: probe values for
// iteration f are loaded during iteration f-1 (breaks LDS->use stalls).
template<int JN>
__device__ __forceinline__ void run_batch(uint32_t aA0, uint32_t aB0, uint32_t aQT,
                                          u64 biasp, u64 EPS2,
                                          float* __restrict__ out, int q0, int p) {
    u64 acc[JN];
#pragma unroll
    for (int j = 0; j < JN; j++) acc[j] = biasp;

    // prologue: load probe f=0
    u64 Pr, Pi, w, mw;
    asm("ld.shared.v2.b64 {%0,%1}, [%2];" : "=l"(Pr), "=l"(Pi) : "r"(aA0));
    asm("ld.shared.v2.b64 {%0,%1}, [%2];" : "=l"(w),  "=l"(mw) : "r"(aB0));

#pragma unroll 2
    for (int f = 0; f < NF; f++) {
        // q-table loads for this f (front-batched, broadcast)
        float tx[JN], ty[JN], tz[JN], tw_[JN];
#pragma unroll
        for (int j = 0; j < JN; j++) {
            asm("ld.shared.v4.f32 {%0,%1,%2,%3}, [%4];"
                : "=f"(tx[j]), "=f"(ty[j]), "=f"(tz[j]), "=f"(tw_[j])
                : "r"(aQT + (uint32_t)j * 1024u + (uint32_t)f * 16u));
        }

        // prefetch probe for f+1 (consumed next iteration)
        u64 PrN, PiN, wN, mwN;
        if (f + 1 < NF) {
            const uint32_t fn = (uint32_t)(f + 1) * 1024u;
            asm("ld.shared.v2.b64 {%0,%1}, [%2];" : "=l"(PrN), "=l"(PiN) : "r"(aA0 + fn));
            asm("ld.shared.v2.b64 {%0,%1}, [%2];" : "=l"(wN),  "=l"(mwN) : "r"(aB0 + fn));
        } else {
            PrN = Pr; PiN = Pi; wN = w; mwN = mw;
        }

#pragma unroll
        for (int j = 0; j < JN; j++) {
            u64 nqr = f2pk(tx[j], tx[j]);
            u64 nqi = f2pk(ty[j], ty[j]);
            u64 qm2 = f2pk(tz[j], tz[j]);
            u64 er = f2add(Pr, nqr);
            u64 ei = f2add(Pi, nqi);
            u64 d2 = f2fma(er, er, f2fma(ei, ei, EPS2));
            float lo, hi; f2upk(lo, hi, d2);
            u64 dist = f2pk(sqrt_apx(lo), sqrt_apx(hi));
            acc[j] = f2fma(dist, w, acc[j]);
            acc[j] = f2fma(qm2, mw, acc[j]);
        }

        Pr = PrN; Pi = PiN; w = wN; mw = mwN;
    }

#pragma unroll
    for (int j = 0; j < JN; j++) {
        float o0, o1; f2upk(o0, o1, acc[j]);
        float* orow = out + (size_t)(q0 + j) * NB;
        orow[p]      = o0;
        orow[p + 64] = o1;
    }
}

__global__ __launch_bounds__(THREADS, 1)
void main_kernel(const float* __restrict__ Q,
                 const float* __restrict__ bias,
                 float* __restrict__ out) {
    extern __shared__ float sm[];
    const int tid  = threadIdx.x;
    const int warp = tid >> 5;
    const int lane = tid & 31;
    const int pid  = warp >> 1;     // pair id 0..11
    const int h    = warp & 1;      // warp half within pair
    const int p    = lane + 32 * h; // b-pair index 0..63

    // Stage probe tables into SMEM
    {
        const float4* gA = (const float4*)g_probeA;
        const float4* gB = (const float4*)g_probeB;
        float4* sA4 = (float4*)(sm + OFF_SA);
        float4* sB4 = (float4*)(sm + OFF_SB);
        for (int i = tid; i < NF * 64; i += THREADS) {
            sA4[i] = gA[i];
            sB4[i] = gB[i];
        }
    }

    const u64 biasp = f2pk(bias[p], bias[p + 64]);
    const u64 EPS2  = f2pk(EPSF, EPSF);

    __syncthreads();

    const uint32_t sbase = su32(sm);
    const uint32_t aA0 = sbase + (uint32_t)p * 16u;
    const uint32_t aB0 = sbase + (uint32_t)OFF_SB * 4u + (uint32_t)p * 16u;
    const uint32_t aQT = sbase + (uint32_t)OFF_QT * 4u + (uint32_t)pid * (MAXQ * 64u * 16u);
    float*  qn = sm + OFF_QN + warp * 128;
    float4* qt = (float4*)(sm + OFF_QT + pid * MAXQ * 64 * 4);

    // ---- contiguous q-range assignment per warp-pair (balanced to +/-1 q) ----
    const int npairs = gridDim.x * PAIRS_PER_CTA;
    const int gp = blockIdx.x * PAIRS_PER_CTA + pid;
    const int per = NQ / npairs;
    const int rem = NQ % npairs;
    int cnt, q0;
    if (gp < rem) { cnt = per + 1; q0 = gp * (per + 1); }
    else          { cnt = per;     q0 = rem * (per + 1) + (gp - rem) * per; }

    while (cnt > 0) {
        const int jn = (cnt > MAXQ) ? MAXQ : cnt;   // 9 -> 5+4, 8 -> 5+3

        // ---- batch prep: warps of the pair split the q's by parity of j ----
        for (int j = h; j < jn; j += 2) {
            const float4* Qv = (const float4*)(Q + (size_t)(q0 + j) * HD);
            float4 v = Qv[lane];
            float ss = fmaf(v.x, v.x, fmaf(v.y, v.y, fmaf(v.z, v.z, v.w * v.w)));
#pragma unroll
            for (int o = 16; o; o >>= 1) ss += __shfl_xor_sync(0xffffffffu, ss, o);
            float inv = rcp_apx(sqrt_apx(ss) + EPSF);
            ((float4*)qn)[lane] = make_float4(v.x * inv, v.y * inv, v.z * inv, v.w * inv);
            __syncwarp();
#pragma unroll
            for (int k = 0; k < 2; k++) {
                int f = lane + k * 32;
                float qr = qn[f];
                float qi = qn[f + 64];
                float qm = sqrt_apx(fmaf(qr, qr, fmaf(qi, qi, EPSF)));
                qt[j * 64 + f] = make_float4(-qr, -qi, qm, 0.0f);
            }
            __syncwarp();
        }
        // pair-scoped named barrier (ids 1..12; 0 reserved for __syncthreads)
        asm volatile("bar.sync %0, %1;" :: "r"(pid + 1), "r"(64) : "memory");

        switch (jn) {
            case 5: run_batch<5>(aA0, aB0, aQT, biasp, EPS2, out, q0, p); break;
            case 4: run_batch<4>(aA0, aB0, aQT, biasp, EPS2, out, q0, p); break;
            case 3: run_batch<3>(aA0, aB0, aQT, biasp, EPS2, out, q0, p); break;
            case 2: run_batch<2>(aA0, aB0, aQT, biasp, EPS2, out, q0, p); break;
            default: run_batch<1>(aA0, aB0, aQT, biasp, EPS2, out, q0, p); break;
        }

        // protect qt against next batch's overwrite while partner still reads
        asm volatile("bar.sync %0, %1;" :: "r"(pid + 1), "r"(64) : "memory");

        q0 += jn;
        cnt -= jn;
    }
}

extern "C" void kernel_launch(void* const* d_in, const int* in_sizes, int n_in,
                              void* d_out, int out_size) {
    const float* Q      = (const float*)d_in[0];
    const float* angles = (const float*)d_in[1];
    const float* probes = (const float*)d_in[2];
    const float* qw     = (const float*)d_in[3];
    const float* qmw    = (const float*)d_in[4];
    const float* qbias  = (const float*)d_in[5];
    float* out = (float*)d_out;

    static_assert(SMEM_FLOATS * sizeof(float) == 204800, "smem layout");
    static_assert(OFF_QT + PAIRS_PER_CTA * MAXQ * 64 * 4 <= OFF_QN, "qt overlap");
    static_assert(OFF_QN + WARPS_PER_CTA * 128 <= SMEM_FLOATS, "qn overlap");

    cudaFuncSetAttribute(main_kernel,
                         cudaFuncAttributeMaxDynamicSharedMemorySize,
                         SMEM_FLOATS * (int)sizeof(float));

    int sms = 148;
    cudaDeviceGetAttribute(&sms, cudaDevAttrMultiProcessorCount, 0);

    prep_kernel<<<NB, 64>>>(probes, angles, qw, qmw);
    main_kernel<<<sms, THREADS, SMEM_FLOATS * sizeof(float)>>>(Q, qbias, out);
}